// round 1
// baseline (speedup 1.0000x reference)
#include <cuda_runtime.h>
#include <cuda_bf16.h>
#include <mma.h>
#include <math.h>

using namespace nvcuda;

// Problem constants
#define NN 50000
#define NE 800000
#define F  128
#define R  8
#define K1 (R*F)      // 1024
#define KTOT (K1+F)   // 1152

// ---------------- device scratch (no cudaMalloc allowed) ----------------
__device__ float g_T[(size_t)NN * K1];   // per-node per-relation sums [N, R*F]
__device__ float g_h1[(size_t)NN * F];   // layer-1 output
__device__ int   g_deg[NN];
__device__ int   g_off[NN + 1];
__device__ int   g_cur[NN];
__device__ int2  g_csr[NE];              // (src, rel) sorted by dst
__device__ float g_pool[F];

// ---------------- CSR build ----------------
__global__ void k_zero() {
    int i = blockIdx.x * blockDim.x + threadIdx.x;
    if (i < NN) g_deg[i] = 0;
    if (i < F)  g_pool[i] = 0.f;
}

__global__ void k_hist(const int* __restrict__ dst) {
    int e = blockIdx.x * blockDim.x + threadIdx.x;
    if (e < NE) atomicAdd(&g_deg[dst[e]], 1);
}

// single-block exclusive scan over g_deg -> g_off / g_cur
__global__ void k_scan() {
    __shared__ int warp_sums[32];
    const int TPB = 1024;
    int t = threadIdx.x;
    int chunk = (NN + TPB - 1) / TPB;          // 49
    int begin = t * chunk;
    int end = begin + chunk; if (end > NN) end = NN;
    int s = 0;
    for (int i = begin; i < end && i < NN; i++) s += g_deg[i];
    int lane = t & 31, wid = t >> 5;
    int v = s;
    #pragma unroll
    for (int o = 1; o < 32; o <<= 1) { int u = __shfl_up_sync(~0u, v, o); if (lane >= o) v += u; }
    if (lane == 31) warp_sums[wid] = v;
    __syncthreads();
    if (wid == 0) {
        int w = warp_sums[lane];
        #pragma unroll
        for (int o = 1; o < 32; o <<= 1) { int u = __shfl_up_sync(~0u, w, o); if (lane >= o) w += u; }
        warp_sums[lane] = w;
    }
    __syncthreads();
    int excl = v - s + (wid > 0 ? warp_sums[wid - 1] : 0);
    int run = excl;
    for (int i = begin; i < end && i < NN; i++) {
        int d = g_deg[i];
        g_off[i] = run; g_cur[i] = run;
        run += d;
    }
    if (t == TPB - 1) g_off[NN] = run;
}

__global__ void k_scatter(const int* __restrict__ src, const int* __restrict__ dst,
                          const int* __restrict__ et) {
    int e = blockIdx.x * blockDim.x + threadIdx.x;
    if (e < NE) {
        int p = atomicAdd(&g_cur[dst[e]], 1);
        g_csr[p] = make_int2(src[e], et[e]);
    }
}

// ---------------- per-node per-relation aggregation: T[n, r*128+d] ----------------
// one warp per node, 8 warps per block, smem accumulators (dynamic rel index)
__global__ void k_agg(const float* __restrict__ hin_ext, int layer) {
    __shared__ float4 acc[8][R * 32];   // 8 warps * 8 rel * 32 float4 = 32KB
    int warp = threadIdx.x >> 5, lane = threadIdx.x & 31;
    int n = blockIdx.x * 8 + warp;
    const float4* hin = (const float4*)(layer == 0 ? hin_ext : (const float*)g_h1);
    if (n >= NN) return;
    float4* a = acc[warp];
    #pragma unroll
    for (int r = 0; r < R; r++) a[r * 32 + lane] = make_float4(0.f, 0.f, 0.f, 0.f);
    int e0 = g_off[n], e1 = g_off[n + 1];
    for (int e = e0; e < e1; e++) {
        int2 sr = make_int2(0, 0);
        if (lane == 0) sr = g_csr[e];
        sr.x = __shfl_sync(0xffffffffu, sr.x, 0);
        sr.y = __shfl_sync(0xffffffffu, sr.y, 0);
        float4 v = hin[(size_t)sr.x * 32 + lane];
        float4& d = a[sr.y * 32 + lane];
        d.x += v.x; d.y += v.y; d.z += v.z; d.w += v.w;
    }
    float4* Tr = (float4*)&g_T[(size_t)n * K1];
    #pragma unroll
    for (int r = 0; r < R; r++) Tr[r * 32 + lane] = a[r * 32 + lane];
}

// ---------------- fused GEMM: out = relu(T @ Wcat + hin @ Wself + b) ----------------
// C tile 128x128 per block, 256 threads = 8 warps (2x4), wmma 16x16x8 tf32.
// layer==0: write g_h1.  layer==1: reduce columns into g_pool (mean pooling fused).
#define GEMM_SMEM (2 * 128 * 132 * 4)

__global__ void k_gemm(const float* __restrict__ hin_ext,
                       const float* __restrict__ W,      // [1024,128] (= [8,128,128])
                       const float* __restrict__ Wself,  // [128,128]
                       const float* __restrict__ bias,   // [128]
                       int layer) {
    extern __shared__ float sm[];
    float* sA = sm;                  // [128][132]
    float* sB = sm + 128 * 132;      // [128][132]
    const float* hin = (layer == 0) ? hin_ext : (const float*)g_h1;
    int m0 = blockIdx.x * 128;
    int t = threadIdx.x;
    int warp = t >> 5;
    int wm = warp & 1;     // 2 tiles in M (64 rows each)
    int wn = warp >> 1;    // 4 tiles in N (32 cols each)

    wmma::fragment<wmma::accumulator, 16, 16, 8, float> c[4][2];
    #pragma unroll
    for (int i = 0; i < 4; i++)
        #pragma unroll
        for (int j = 0; j < 2; j++) wmma::fill_fragment(c[i][j], 0.f);

    for (int kb = 0; kb < 9; kb++) {
        const float* Abase; int lda;
        if (kb < 8) { Abase = g_T + (size_t)m0 * K1 + kb * 128; lda = K1; }
        else        { Abase = hin + (size_t)m0 * F;             lda = F; }
        const float* Bbase = (kb < 8) ? (W + (size_t)kb * 128 * 128) : Wself;

        #pragma unroll
        for (int i = 0; i < 16; i++) {
            int idx = t + i * 256;           // 0..4095 float4 slots
            int row = idx >> 5;
            int c4  = idx & 31;
            float4 v = make_float4(0.f, 0.f, 0.f, 0.f);
            if (m0 + row < NN) v = *(const float4*)(Abase + (size_t)row * lda + c4 * 4);
            float* dp = sA + row * 132 + c4 * 4;
            dp[0] = wmma::__float_to_tf32(v.x);
            dp[1] = wmma::__float_to_tf32(v.y);
            dp[2] = wmma::__float_to_tf32(v.z);
            dp[3] = wmma::__float_to_tf32(v.w);
        }
        #pragma unroll
        for (int i = 0; i < 16; i++) {
            int idx = t + i * 256;
            int row = idx >> 5;
            int c4  = idx & 31;
            float4 v = *(const float4*)(Bbase + row * 128 + c4 * 4);
            float* dp = sB + row * 132 + c4 * 4;
            dp[0] = wmma::__float_to_tf32(v.x);
            dp[1] = wmma::__float_to_tf32(v.y);
            dp[2] = wmma::__float_to_tf32(v.z);
            dp[3] = wmma::__float_to_tf32(v.w);
        }
        __syncthreads();

        #pragma unroll
        for (int ks = 0; ks < 16; ks++) {
            wmma::fragment<wmma::matrix_a, 16, 16, 8, wmma::precision::tf32, wmma::row_major> af[4];
            wmma::fragment<wmma::matrix_b, 16, 16, 8, wmma::precision::tf32, wmma::row_major> bf[2];
            #pragma unroll
            for (int i = 0; i < 4; i++)
                wmma::load_matrix_sync(af[i], sA + (wm * 64 + i * 16) * 132 + ks * 8, 132);
            #pragma unroll
            for (int j = 0; j < 2; j++)
                wmma::load_matrix_sync(bf[j], sB + (ks * 8) * 132 + wn * 32 + j * 16, 132);
            #pragma unroll
            for (int i = 0; i < 4; i++)
                #pragma unroll
                for (int j = 0; j < 2; j++)
                    wmma::mma_sync(c[i][j], af[i], bf[j], c[i][j]);
        }
        __syncthreads();
    }

    // epilogue: dump C into sA, apply bias+relu
    #pragma unroll
    for (int i = 0; i < 4; i++)
        #pragma unroll
        for (int j = 0; j < 2; j++)
            wmma::store_matrix_sync(sA + (wm * 64 + i * 16) * 132 + wn * 32 + j * 16,
                                    c[i][j], 132, wmma::mem_row_major);
    __syncthreads();

    if (layer == 0) {
        #pragma unroll
        for (int i = 0; i < 16; i++) {
            int idx = t + i * 256;
            int row = idx >> 5;
            int c4  = idx & 31;
            if (m0 + row < NN) {
                float* sp = sA + row * 132 + c4 * 4;
                float4 v;
                v.x = fmaxf(sp[0] + bias[c4 * 4 + 0], 0.f);
                v.y = fmaxf(sp[1] + bias[c4 * 4 + 1], 0.f);
                v.z = fmaxf(sp[2] + bias[c4 * 4 + 2], 0.f);
                v.w = fmaxf(sp[3] + bias[c4 * 4 + 3], 0.f);
                *(float4*)(g_h1 + (size_t)(m0 + row) * F + c4 * 4) = v;
            }
        }
    } else {
        // fused mean-pool: column sums over valid rows
        int col = t & 127;
        int rh = t >> 7;            // 0 or 1 -> row halves
        float bc = bias[col];
        float s = 0.f;
        for (int r = rh * 64; r < rh * 64 + 64; r++) {
            if (m0 + r < NN) s += fmaxf(sA[r * 132 + col] + bc, 0.f);
        }
        atomicAdd(&g_pool[col], s);
    }
}

// ---------------- final: logits = mean-pool . fc_w + fc_b ; sigmoid ----------------
__global__ void k_final(const float* __restrict__ fc_w, const float* __restrict__ fc_b,
                        float* __restrict__ out) {
    __shared__ float red[F];
    int t = threadIdx.x;
    float v = g_pool[t] * (1.f / (float)NN) * fc_w[t];
    red[t] = v;
    __syncthreads();
    for (int o = 64; o > 0; o >>= 1) {
        if (t < o) red[t] += red[t + o];
        __syncthreads();
    }
    if (t == 0) {
        float logit = red[0] + fc_b[0];
        out[0] = 1.f / (1.f + expf(-logit));
    }
}

// ---------------- launch ----------------
extern "C" void kernel_launch(void* const* d_in, const int* in_sizes, int n_in,
                              void* d_out, int out_size) {
    const float* in_feat = (const float*)d_in[0];
    const float* W1   = (const float*)d_in[1];
    const float* W1s  = (const float*)d_in[2];
    const float* b1   = (const float*)d_in[3];
    const float* W2   = (const float*)d_in[4];
    const float* W2s  = (const float*)d_in[5];
    const float* b2   = (const float*)d_in[6];
    const float* fcw  = (const float*)d_in[7];
    const float* fcb  = (const float*)d_in[8];
    const int*   src  = (const int*)d_in[9];
    const int*   dst  = (const int*)d_in[10];
    const int*   et   = (const int*)d_in[11];
    float* out = (float*)d_out;

    cudaFuncSetAttribute(k_gemm, cudaFuncAttributeMaxDynamicSharedMemorySize, GEMM_SMEM);

    k_zero<<<(NN + 255) / 256, 256>>>();
    k_hist<<<(NE + 255) / 256, 256>>>(dst);
    k_scan<<<1, 1024>>>();
    k_scatter<<<(NE + 255) / 256, 256>>>(src, dst, et);

    const int gemm_grid = (NN + 127) / 128;   // 391

    // Layer 1
    k_agg<<<(NN + 7) / 8, 256>>>(in_feat, 0);
    k_gemm<<<gemm_grid, 256, GEMM_SMEM>>>(in_feat, W1, W1s, b1, 0);

    // Layer 2 (pooling fused into epilogue)
    k_agg<<<(NN + 7) / 8, 256>>>(nullptr, 1);
    k_gemm<<<gemm_grid, 256, GEMM_SMEM>>>(nullptr, W2, W2s, b2, 1);

    k_final<<<1, 128>>>(fcw, fcb, out);
}